// round 9
// baseline (speedup 1.0000x reference)
#include <cuda_runtime.h>
#include <cstdint>

// Problem constants
#define Tn   1024
#define Bn   64
#define Dn   32
#define Hn   512
#define KK   544            // H + D concatenated K
#define NG   4              // independent batch groups
#define GC   32             // CTAs per group
#define BG   16             // batches per group
#define HB2  (Hn * BG)      // 8192 floats per group-step
#define NCTA 128
#define NTHR 256
#define RPAD 68

// Device-global scratch (zero-initialized at module load)
__device__ float g_xT  [(size_t)Tn * Dn * Bn];               // [t][d][b]
__device__ float g_hist[(size_t)(Tn + 1) * NG * HB2];        // [t][g][h][bl]
__device__ __align__(128) unsigned g_flags[NCTA * 32];       // 1 flag / 128B line

// SMEM layout (floats)
#define SM_W    (KK * 64)        // W slice k-major [k][r]        139264 B
#define SM_HD   (KK * 32)        // (h|x) duplicated [k][(b,b)]    69632 B
#define SM_R    (4 * 16 * RPAD)  // k-seg partials [seg][b][rpad]  17408 B
#define SM_G    (16 * RPAD)      // reduced gates [b][rpad]         4352 B
#define SM_BIAS 64
#define SMEM_FLOATS (SM_W + SM_HD + SM_R + SM_G + SM_BIAS)
#define SMEM_BYTES  (SMEM_FLOATS * 4)

__device__ __forceinline__ float fsigmoid(float x) {
    return 1.f / (1.f + __expf(-x));
}
__device__ __forceinline__ float ftanh_(float x) {
    return 1.f - 2.f / (__expf(2.f * x) + 1.f);
}

// One-time waits (preamble/tail): lane-parallel poll with backoff
__device__ __forceinline__ void poll_flag_sleep(const unsigned* fptr,
                                                unsigned tgt) {
    for (;;) {
        unsigned v;
        asm volatile("ld.acquire.gpu.global.u32 %0, [%1];"
                     : "=r"(v) : "l"(fptr) : "memory");
        if (!__any_sync(0xFFFFFFFFu, (int)(v - tgt) < 0)) break;
        __nanosleep(32);
    }
}

__device__ __forceinline__ void publish(unsigned* flag, unsigned val) {
    asm volatile("st.release.gpu.global.u32 [%0], %1;"
                 :: "l"(flag), "r"(val) : "memory");
}

extern __shared__ float smem[];

// ===========================================================================
// ONE fused persistent kernel: transpose + init + LSTM recurrence + conv
// ===========================================================================
__global__ void __launch_bounds__(NTHR, 1) lstm_fused_kernel(
    const float* __restrict__ x,      // (B, D, T)
    const float* __restrict__ W_ih,   // (4H, D)
    const float* __restrict__ W_hh,   // (4H, H)
    const float* __restrict__ b_ih,   // (4H,)
    const float* __restrict__ b_hh,   // (4H,)
    const float* __restrict__ cw,     // (1, H, 1)
    const float* __restrict__ cb,     // (1,)
    float* __restrict__ out)          // (B, 1, T)
{
    float* sm_w    = smem;                     // [544 k][64 r]
    float* sm_hd   = smem + SM_W;              // [544 k][32] (16 b dup)
    float* sm_r    = sm_hd + SM_HD;            // [4 seg][16 b][RPAD]
    float* sm_g    = sm_r + SM_R;              // [16 b][RPAD]
    float* sm_bias = sm_g + SM_G;              // [64]

    const int tid = threadIdx.x;
    const int cta = blockIdx.x;
    const int g   = cta >> 5;                  // group 0..3
    const int c   = cta & 31;                  // cta within group

    // Epoch base (all CTAs end each replay at base + Tn + 1)
    const unsigned base = g_flags[cta * 32];

    // ---- phase A: transpose x (B,D,T) -> g_xT (T,D,B); this CTA's 1/128 ----
    {
        const float4* x4 = (const float4*)x;
        for (int i = tid; i < 4096; i += NTHR) {
            int idx4 = cta * 4096 + i;
            float4 v = __ldcg(x4 + idx4);
            int t0 = (idx4 & 255) * 4;
            int d  = (idx4 >> 8) & 31;
            int b  = idx4 >> 13;
            float* dst = g_xT + d * 64 + b;
            dst[(size_t)(t0 + 0) * 2048] = v.x;
            dst[(size_t)(t0 + 1) * 2048] = v.y;
            dst[(size_t)(t0 + 2) * 2048] = v.z;
            dst[(size_t)(t0 + 3) * 2048] = v.w;
        }
    }
    // zero own h(0) rows
    g_hist[(size_t)g * HB2 + c * 256 + tid] = 0.f;

    // ---- load W slice k-major (+ bias) ----
    for (int r = 0; r < 64; ++r) {
        int n = (r >> 4) * Hn + c * 16 + (r & 15);
        for (int k = tid; k < KK; k += NTHR) {
            float w = (k < Hn) ? W_hh[(size_t)n * Hn + k]
                               : W_ih[(size_t)n * Dn + (k - Hn)];
            sm_w[k * 64 + r] = w;
        }
    }
    if (tid < 64) {
        int n = (tid >> 4) * Hn + c * 16 + (tid & 15);
        sm_bias[tid] = b_ih[n] + b_hh[n];
    }

    __syncthreads();
    if (tid == 0) publish(&g_flags[cta * 32], base + 1);
    // wait for ALL 128 CTAs (transpose is global)
    if (tid < 128) poll_flag_sleep(&g_flags[tid * 32], base + 1);
    __syncthreads();

    // ---- pre-stage h_0 + x_0 (full burst, duplicated) ----
    {
        const float4* src = (const float4*)(g_hist + (size_t)g * HB2);
        #pragma unroll
        for (int i = 0; i < 8; ++i) {
            int idx = tid + i * NTHR;
            float4 v = __ldcg(src + idx);
            int k = idx >> 2, q = idx & 3;
            float4* d0 = (float4*)(sm_hd + k * 32 + q * 8);
            d0[0] = make_float4(v.x, v.x, v.y, v.y);
            d0[1] = make_float4(v.z, v.z, v.w, v.w);
        }
        if (tid < 128) {
            int d = tid >> 2, q = tid & 3;
            const float4* sx = (const float4*)(g_xT + d * 64 + g * 16);
            float4 v = __ldcg(sx + q);
            float4* d0 = (float4*)(sm_hd + (512 + d) * 32 + q * 8);
            d0[0] = make_float4(v.x, v.x, v.y, v.y);
            d0[1] = make_float4(v.z, v.z, v.w, v.w);
        }
    }

    // ---- GEMM mapping ----
    const int seg = tid >> 6;                          // k-segment 0..3
    const int tq  = tid & 63;
    const int npp = tq >> 2;                           // r-quad 0..15
    const int bq  = tq & 3;                            // b-quad 0..3
    const int kb  = (seg < 2) ? seg * 128 : 256 + (seg - 2) * 144;
    const int ke  = kb + ((seg < 2) ? 128 : 144);
    const ulonglong2* wp = (const ulonglong2*)sm_w;    // + k*16 + npp
    const ulonglong2* hp = (const ulonglong2*)sm_hd;   // + k*8  + bq*2

    // epilogue mapping (warps 0-1 only): 4 cell states per thread
    const int ebl  = tid & 15;       // batch
    const int ehl4 = tid >> 4;       // hl = ehl4*4 + p
    float c_reg[4] = {0.f, 0.f, 0.f, 0.f};

    for (int t = 0; t < Tn; ++t) {
        __syncthreads();   // sm_hd fully staged (prev iter / pre-stage)

        // ---- GEMM segment: acc (4r x 4b) as 8 f32x2 ----
        unsigned long long a0 = 0, a1 = 0, a2 = 0, a3 = 0;
        unsigned long long a4 = 0, a5 = 0, a6 = 0, a7 = 0;
        #pragma unroll 8
        for (int k = kb; k < ke; ++k) {
            ulonglong2 w2 = wp[k * 16 + npp];
            ulonglong2 h0 = hp[k * 8 + bq * 2];
            ulonglong2 h1 = hp[k * 8 + bq * 2 + 1];
            asm("fma.rn.f32x2 %0, %1, %2, %0;" : "+l"(a0) : "l"(w2.x), "l"(h0.x));
            asm("fma.rn.f32x2 %0, %1, %2, %0;" : "+l"(a1) : "l"(w2.x), "l"(h0.y));
            asm("fma.rn.f32x2 %0, %1, %2, %0;" : "+l"(a2) : "l"(w2.x), "l"(h1.x));
            asm("fma.rn.f32x2 %0, %1, %2, %0;" : "+l"(a3) : "l"(w2.x), "l"(h1.y));
            asm("fma.rn.f32x2 %0, %1, %2, %0;" : "+l"(a4) : "l"(w2.y), "l"(h0.x));
            asm("fma.rn.f32x2 %0, %1, %2, %0;" : "+l"(a5) : "l"(w2.y), "l"(h0.y));
            asm("fma.rn.f32x2 %0, %1, %2, %0;" : "+l"(a6) : "l"(w2.y), "l"(h1.x));
            asm("fma.rn.f32x2 %0, %1, %2, %0;" : "+l"(a7) : "l"(w2.y), "l"(h1.y));
        }

        // ---- store partials [seg][b][r] ----
        {
            float2 p0 = *(float2*)&a0, p4 = *(float2*)&a4;
            float2 p1 = *(float2*)&a1, p5 = *(float2*)&a5;
            float2 p2 = *(float2*)&a2, p6 = *(float2*)&a6;
            float2 p3 = *(float2*)&a3, p7 = *(float2*)&a7;
            float* bp = sm_r + (seg * 16 + bq * 4) * RPAD + npp * 4;
            *(float4*)(bp + 0 * RPAD) = make_float4(p0.x, p0.y, p4.x, p4.y);
            *(float4*)(bp + 1 * RPAD) = make_float4(p1.x, p1.y, p5.x, p5.y);
            *(float4*)(bp + 2 * RPAD) = make_float4(p2.x, p2.y, p6.x, p6.y);
            *(float4*)(bp + 3 * RPAD) = make_float4(p3.x, p3.y, p7.x, p7.y);
        }
        __syncthreads();

        // ---- reduce 4 segments -> sm_g[b][r] (all 256 threads) ----
        {
            int b = tid >> 4, nq = tid & 15;
            const float* rb = sm_r + b * RPAD + nq * 4;
            float4 s0 = *(const float4*)(rb);
            float4 s1 = *(const float4*)(rb + 16 * RPAD);
            float4 s2 = *(const float4*)(rb + 32 * RPAD);
            float4 s3 = *(const float4*)(rb + 48 * RPAD);
            *(float4*)(sm_g + b * RPAD + nq * 4) =
                make_float4(s0.x + s1.x + s2.x + s3.x,
                            s0.y + s1.y + s2.y + s3.y,
                            s0.z + s1.z + s2.z + s3.z,
                            s0.w + s1.w + s2.w + s3.w);
        }
        __syncthreads();

        if (tid < 64) {
            // ===== warps 0-1: epilogue + own-block write + publish =====
            float* gdst = g_hist + ((size_t)(t + 1) * NG + g) * HB2;
            #pragma unroll
            for (int p = 0; p < 4; ++p) {
                int hl = ehl4 * 4 + p;
                float xi = sm_g[ebl * RPAD +  0 + hl] + sm_bias[ 0 + hl];
                float xf = sm_g[ebl * RPAD + 16 + hl] + sm_bias[16 + hl];
                float xg = sm_g[ebl * RPAD + 32 + hl] + sm_bias[32 + hl];
                float xo = sm_g[ebl * RPAD + 48 + hl] + sm_bias[48 + hl];
                float ii = fsigmoid(xi);
                float ff = fsigmoid(xf);
                float gg = ftanh_(xg);
                float oo = fsigmoid(xo);
                c_reg[p] = ff * c_reg[p] + ii * gg;
                float h = oo * ftanh_(c_reg[p]);
                gdst[(c * 16 + hl) * BG + ebl] = h;
                // own rows into sm_hd straight from registers
                *(float2*)(sm_hd + (c * 16 + hl) * 32 + ebl * 2) =
                    make_float2(h, h);
            }
            asm volatile("bar.sync 3, 64;" ::: "memory");
            if (tid == 0) publish(&g_flags[cta * 32], base + (unsigned)t + 2);
        } else {
            // ===== warps 2-7: stage x_{t+1} + other CTAs' h_{t+1} =====
            if (tid < 192 && t + 1 < Tn) {     // x chunk (static data)
                int idx = tid - 64;            // 0..127
                int d = idx >> 2, q = idx & 3;
                const float4* sx = (const float4*)
                    (g_xT + (size_t)(t + 1) * 2048 + d * 64 + g * 16);
                float4 v = __ldcg(sx + q);
                float4* d0 = (float4*)(sm_hd + (512 + d) * 32 + q * 8);
                d0[0] = make_float4(v.x, v.x, v.y, v.y);
                d0[1] = make_float4(v.z, v.z, v.w, v.w);
            }
            const int w    = tid >> 5;         // 2..7
            const int lane = tid & 31;
            const float4* hsrc = (const float4*)
                (g_hist + ((size_t)(t + 1) * NG + g) * HB2);
            const unsigned tgt = base + (unsigned)t + 2;
            for (int j = w - 2; j < 32; j += 6) {
                if (j == c) continue;
                const unsigned* fp = &g_flags[(g * 32 + j) * 32];
                unsigned v;
                do {
                    asm volatile("ld.acquire.gpu.global.u32 %0, [%1];"
                                 : "=r"(v) : "l"(fp) : "memory");
                } while ((int)(v - tgt) < 0);
                #pragma unroll
                for (int m = 0; m < 2; ++m) {
                    int f = lane + m * 32;               // 0..63
                    float4 hv = __ldcg(hsrc + j * 64 + f);
                    int kl = f >> 2, q = f & 3;
                    float4* d0 = (float4*)(sm_hd + (j * 16 + kl) * 32 + q * 8);
                    d0[0] = make_float4(hv.x, hv.x, hv.y, hv.y);
                    d0[1] = make_float4(hv.z, hv.z, hv.w, hv.w);
                }
            }
        }
    }

    // ================= conv tail =================
    if (tid < 32)
        poll_flag_sleep(&g_flags[(g * 32 + tid) * 32], base + Tn + 1);
    __syncthreads();

    float* scw  = sm_w;      // reuse
    float* sred = sm_r;
    for (int i = tid; i < Hn; i += NTHR) scw[i] = cw[i];
    const float cbv = cb[0];
    __syncthreads();

    const int cbl = tid & 15, hq = tid >> 4;     // 16 h-chunks of 32
    for (int j = 0; j < Tn / GC; ++j) {
        int t = c * (Tn / GC) + j;
        const float* hp2 = g_hist + ((size_t)(t + 1) * NG + g) * HB2 + cbl;
        float acc = 0.f;
        #pragma unroll 8
        for (int h = hq * 32; h < hq * 32 + 32; ++h)
            acc += __ldcg(hp2 + (size_t)h * BG) * scw[h];
        sred[tid] = acc;
        __syncthreads();
        if (tid < 16) {
            float s = cbv;
            #pragma unroll
            for (int q = 0; q < 16; ++q) s += sred[q * 16 + tid];
            out[(size_t)(g * 16 + tid) * Tn + t] = s;
        }
        __syncthreads();
    }
}

// ---------------------------------------------------------------------------
extern "C" void kernel_launch(void* const* d_in, const int* in_sizes, int n_in,
                              void* d_out, int out_size)
{
    const float* x    = (const float*)d_in[0];
    const float* W_ih = (const float*)d_in[1];
    const float* W_hh = (const float*)d_in[2];
    const float* b_ih = (const float*)d_in[3];
    const float* b_hh = (const float*)d_in[4];
    const float* cw   = (const float*)d_in[5];
    const float* cb   = (const float*)d_in[6];
    float* out = (float*)d_out;

    cudaFuncSetAttribute(lstm_fused_kernel,
                         cudaFuncAttributeMaxDynamicSharedMemorySize, SMEM_BYTES);
    lstm_fused_kernel<<<NCTA, NTHR, SMEM_BYTES>>>(x, W_ih, W_hh, b_ih, b_hh,
                                                  cw, cb, out);
}

// round 10
// speedup vs baseline: 1.3768x; 1.3768x over previous
#include <cuda_runtime.h>
#include <cstdint>

// Problem constants
#define Tn   1024
#define Bn   64
#define Dn   32
#define Hn   512
#define KK   544            // H + D concatenated K
#define NG   4              // independent batch groups
#define GC   32             // CTAs per group
#define BG   16             // batches per group
#define HB2  (Hn * BG)      // 8192 floats per group-step
#define NCTA 128
#define NTHR 256
#define RPAD 68

// Device-global scratch (zero-initialized at module load)
__device__ float g_xT  [(size_t)Tn * Dn * Bn];               // [t][d][b]
__device__ float g_hist[(size_t)(Tn + 1) * NG * HB2];        // [t][g][h][bl]
__device__ __align__(128) unsigned g_flags[NCTA * 32];       // 1 flag / 128B line

// SMEM layout (floats)
#define SM_W    (KK * 64)        // W slice k-major [k][r]        139264 B
#define SM_HD   (KK * 32)        // (h|x) duplicated [k][(b,b)]    69632 B
#define SM_R    (4 * 16 * RPAD)  // k-seg partials [seg][b][rpad]  17408 B
#define SM_G    (16 * RPAD)      // reduced gates [b][rpad]         4352 B
#define SM_BIAS 64
#define SMEM_FLOATS (SM_W + SM_HD + SM_R + SM_G + SM_BIAS)
#define SMEM_BYTES  (SMEM_FLOATS * 4)

#define L2E 1.4426950408889634f

__device__ __forceinline__ float ex2f(float x) {
    float y; asm("ex2.approx.ftz.f32 %0, %1;" : "=f"(y) : "f"(x)); return y;
}
__device__ __forceinline__ float rcpf(float x) {
    float y; asm("rcp.approx.ftz.f32 %0, %1;" : "=f"(y) : "f"(x)); return y;
}

// One-time waits (preamble/tail): lane-parallel poll with backoff
__device__ __forceinline__ void poll_flag_sleep(const unsigned* fptr,
                                                unsigned tgt) {
    for (;;) {
        unsigned v;
        asm volatile("ld.acquire.gpu.global.u32 %0, [%1];"
                     : "=r"(v) : "l"(fptr) : "memory");
        if (!__any_sync(0xFFFFFFFFu, (int)(v - tgt) < 0)) break;
        __nanosleep(32);
    }
}

__device__ __forceinline__ void publish(unsigned* flag, unsigned val) {
    asm volatile("st.release.gpu.global.u32 [%0], %1;"
                 :: "l"(flag), "r"(val) : "memory");
}

extern __shared__ float smem[];

// ===========================================================================
// ONE fused persistent kernel: transpose + init + LSTM recurrence + conv
// ===========================================================================
__global__ void __launch_bounds__(NTHR, 1) lstm_fused_kernel(
    const float* __restrict__ x,      // (B, D, T)
    const float* __restrict__ W_ih,   // (4H, D)
    const float* __restrict__ W_hh,   // (4H, H)
    const float* __restrict__ b_ih,   // (4H,)
    const float* __restrict__ b_hh,   // (4H,)
    const float* __restrict__ cw,     // (1, H, 1)
    const float* __restrict__ cb,     // (1,)
    float* __restrict__ out)          // (B, 1, T)
{
    float* sm_w    = smem;                     // [544 k][64 r]
    float* sm_hd   = smem + SM_W;              // [544 k][32] (16 b dup)
    float* sm_r    = sm_hd + SM_HD;            // [4 seg][16 b][RPAD]
    float* sm_g    = sm_r + SM_R;              // [16 b][RPAD]
    float* sm_bias = sm_g + SM_G;              // [64]

    const int tid = threadIdx.x;
    const int cta = blockIdx.x;
    const int g   = cta >> 5;                  // group 0..3
    const int c   = cta & 31;                  // cta within group

    // Epoch base (all CTAs end each replay at base + Tn + 1)
    const unsigned base = g_flags[cta * 32];

    // ---- phase A: transpose x (B,D,T) -> g_xT (T,D,B); this CTA's 1/128 ----
    {
        const float4* x4 = (const float4*)x;
        for (int i = tid; i < 4096; i += NTHR) {
            int idx4 = cta * 4096 + i;
            float4 v = __ldcg(x4 + idx4);
            int t0 = (idx4 & 255) * 4;
            int d  = (idx4 >> 8) & 31;
            int b  = idx4 >> 13;
            float* dst = g_xT + d * 64 + b;
            dst[(size_t)(t0 + 0) * 2048] = v.x;
            dst[(size_t)(t0 + 1) * 2048] = v.y;
            dst[(size_t)(t0 + 2) * 2048] = v.z;
            dst[(size_t)(t0 + 3) * 2048] = v.w;
        }
    }
    // zero own h(0) rows
    g_hist[(size_t)g * HB2 + c * 256 + tid] = 0.f;

    // ---- load W slice k-major (+ bias) ----
    for (int r = 0; r < 64; ++r) {
        int n = (r >> 4) * Hn + c * 16 + (r & 15);
        for (int k = tid; k < KK; k += NTHR) {
            float w = (k < Hn) ? W_hh[(size_t)n * Hn + k]
                               : W_ih[(size_t)n * Dn + (k - Hn)];
            sm_w[k * 64 + r] = w;
        }
    }
    if (tid < 64) {
        int n = (tid >> 4) * Hn + c * 16 + (tid & 15);
        sm_bias[tid] = b_ih[n] + b_hh[n];
    }

    __syncthreads();
    if (tid == 0) publish(&g_flags[cta * 32], base + 1);
    // wait for ALL 128 CTAs (transpose is global)
    if (tid < 128) poll_flag_sleep(&g_flags[tid * 32], base + 1);
    __syncthreads();

    // ---- pre-stage h_0 + x_0 (full burst, duplicated) ----
    {
        const float4* src = (const float4*)(g_hist + (size_t)g * HB2);
        #pragma unroll
        for (int i = 0; i < 8; ++i) {
            int idx = tid + i * NTHR;
            float4 v = __ldcg(src + idx);
            int k = idx >> 2, q = idx & 3;
            float4* d0 = (float4*)(sm_hd + k * 32 + q * 8);
            d0[0] = make_float4(v.x, v.x, v.y, v.y);
            d0[1] = make_float4(v.z, v.z, v.w, v.w);
        }
        if (tid < 128) {
            int d = tid >> 2, q = tid & 3;
            const float4* sx = (const float4*)(g_xT + d * 64 + g * 16);
            float4 v = __ldcg(sx + q);
            float4* d0 = (float4*)(sm_hd + (512 + d) * 32 + q * 8);
            d0[0] = make_float4(v.x, v.x, v.y, v.y);
            d0[1] = make_float4(v.z, v.z, v.w, v.w);
        }
    }

    // ---- GEMM mapping ----
    const int seg = tid >> 6;                          // k-segment 0..3
    const int tq  = tid & 63;
    const int npp = tq >> 2;                           // r-quad 0..15
    const int bq  = tq & 3;                            // b-quad 0..3
    const int kb  = (seg < 2) ? seg * 128 : 256 + (seg - 2) * 144;
    const int ke  = kb + ((seg < 2) ? 128 : 144);
    const ulonglong2* wp = (const ulonglong2*)sm_w;    // + k*16 + npp
    const ulonglong2* hp = (const ulonglong2*)sm_hd;   // + k*8  + bq*2

    // epilogue mapping: 1 cell per thread
    const int bl = tid & 15, hl = tid >> 4;
    float c_reg = 0.f;

    // stage mapping
    const int wrp = tid >> 5, lane = tid & 31;

    for (int t = 0; t < Tn; ++t) {
        __syncthreads();   // sm_hd fully staged

        // ---- GEMM segment: acc (4r x 4b) as 8 f32x2 ----
        unsigned long long a0 = 0, a1 = 0, a2 = 0, a3 = 0;
        unsigned long long a4 = 0, a5 = 0, a6 = 0, a7 = 0;
        #pragma unroll 8
        for (int k = kb; k < ke; ++k) {
            ulonglong2 w2 = wp[k * 16 + npp];
            ulonglong2 h0 = hp[k * 8 + bq * 2];
            ulonglong2 h1 = hp[k * 8 + bq * 2 + 1];
            asm("fma.rn.f32x2 %0, %1, %2, %0;" : "+l"(a0) : "l"(w2.x), "l"(h0.x));
            asm("fma.rn.f32x2 %0, %1, %2, %0;" : "+l"(a1) : "l"(w2.x), "l"(h0.y));
            asm("fma.rn.f32x2 %0, %1, %2, %0;" : "+l"(a2) : "l"(w2.x), "l"(h1.x));
            asm("fma.rn.f32x2 %0, %1, %2, %0;" : "+l"(a3) : "l"(w2.x), "l"(h1.y));
            asm("fma.rn.f32x2 %0, %1, %2, %0;" : "+l"(a4) : "l"(w2.y), "l"(h0.x));
            asm("fma.rn.f32x2 %0, %1, %2, %0;" : "+l"(a5) : "l"(w2.y), "l"(h0.y));
            asm("fma.rn.f32x2 %0, %1, %2, %0;" : "+l"(a6) : "l"(w2.y), "l"(h1.x));
            asm("fma.rn.f32x2 %0, %1, %2, %0;" : "+l"(a7) : "l"(w2.y), "l"(h1.y));
        }

        // ---- store partials [seg][b][r] ----
        {
            float2 p0 = *(float2*)&a0, p4 = *(float2*)&a4;
            float2 p1 = *(float2*)&a1, p5 = *(float2*)&a5;
            float2 p2 = *(float2*)&a2, p6 = *(float2*)&a6;
            float2 p3 = *(float2*)&a3, p7 = *(float2*)&a7;
            float* bp = sm_r + (seg * 16 + bq * 4) * RPAD + npp * 4;
            *(float4*)(bp + 0 * RPAD) = make_float4(p0.x, p0.y, p4.x, p4.y);
            *(float4*)(bp + 1 * RPAD) = make_float4(p1.x, p1.y, p5.x, p5.y);
            *(float4*)(bp + 2 * RPAD) = make_float4(p2.x, p2.y, p6.x, p6.y);
            *(float4*)(bp + 3 * RPAD) = make_float4(p3.x, p3.y, p7.x, p7.y);
        }
        __syncthreads();

        // ---- reduce 4 segments -> sm_g[b][r] ----
        {
            int b = tid >> 4, nq = tid & 15;
            const float* rb = sm_r + b * RPAD + nq * 4;
            float4 s0 = *(const float4*)(rb);
            float4 s1 = *(const float4*)(rb + 16 * RPAD);
            float4 s2 = *(const float4*)(rb + 32 * RPAD);
            float4 s3 = *(const float4*)(rb + 48 * RPAD);
            *(float4*)(sm_g + b * RPAD + nq * 4) =
                make_float4(s0.x + s1.x + s2.x + s3.x,
                            s0.y + s1.y + s2.y + s3.y,
                            s0.z + s1.z + s2.z + s3.z,
                            s0.w + s1.w + s2.w + s3.w);
        }
        __syncthreads();

        // ---- LSTM cell epilogue (division-free, 5 EX2 + 3 RCP) ----
        {
            float xi = sm_g[bl * RPAD +  0 + hl] + sm_bias[ 0 + hl];
            float xf = sm_g[bl * RPAD + 16 + hl] + sm_bias[16 + hl];
            float xg = sm_g[bl * RPAD + 32 + hl] + sm_bias[32 + hl];
            float xo = sm_g[bl * RPAD + 48 + hl] + sm_bias[48 + hl];
            float ei = ex2f(-xi * L2E);
            float ef = ex2f(-xf * L2E);
            float eo = ex2f(-xo * L2E);
            float eg = ex2f(-2.f * xg * L2E);
            float di = 1.f + ei, df = 1.f + ef, dc = 1.f + eo, dg = 1.f + eg;
            float r0 = rcpf(di * df);
            float ii = r0 * df, ff = r0 * di;
            float r1 = rcpf(dc * dg);
            float oo = r1 * dg;
            float tg = (1.f - eg) * (r1 * dc);
            c_reg = ff * c_reg + ii * tg;
            float ec = ex2f(-2.f * c_reg * L2E);
            float tc = (1.f - ec) * rcpf(1.f + ec);
            float h  = oo * tc;
            g_hist[((size_t)(t + 1) * NG + g) * HB2 + c * 256 + tid] = h;
            // self-stage own rows straight from registers
            *(float2*)(sm_hd + (c * 16 + hl) * 32 + bl * 2) = make_float2(h, h);
        }
        __syncthreads();
        if (tid == 0) publish(&g_flags[cta * 32], base + (unsigned)t + 2);

        // ---- stage phase for step t+1 (per-warp chunked) ----
        if (t + 1 < Tn) {
            // x_{t+1}: always ready, stage first (16 float4 per warp)
            if (lane < 16) {
                int idx = wrp * 16 + lane;           // 0..127
                int d = idx >> 2, q = idx & 3;
                const float4* sx = (const float4*)
                    (g_xT + (size_t)(t + 1) * 2048 + d * 64 + g * 16);
                float4 v = __ldcg(sx + q);
                float4* d0 = (float4*)(sm_hd + (512 + d) * 32 + q * 8);
                d0[0] = make_float4(v.x, v.x, v.y, v.y);
                d0[1] = make_float4(v.z, v.z, v.w, v.w);
            }
            // poll this warp's 4 source CTAs (lanes 0-3)
            const unsigned tgt = base + (unsigned)t + 2;
            {
                const unsigned* fp = &g_flags[(g * 32 + wrp * 4 + lane) * 32];
                unsigned v = tgt;
                for (;;) {
                    if (lane < 4)
                        asm volatile("ld.acquire.gpu.global.u32 %0, [%1];"
                                     : "=r"(v) : "l"(fp) : "memory");
                    if (__all_sync(0xFFFFFFFFu, (int)(v - tgt) >= 0)) break;
                }
            }
            // stage this warp's 4 chunks (skip own, already self-staged)
            const float4* hsrc = (const float4*)
                (g_hist + ((size_t)(t + 1) * NG + g) * HB2);
            #pragma unroll
            for (int jj = 0; jj < 4; ++jj) {
                int j = wrp * 4 + jj;
                if (j == c) continue;
                #pragma unroll
                for (int m = 0; m < 2; ++m) {
                    int f = lane + m * 32;           // 0..63
                    float4 hv = __ldcg(hsrc + j * 64 + f);
                    int kl = f >> 2, q = f & 3;
                    float4* d0 = (float4*)(sm_hd + (j * 16 + kl) * 32 + q * 8);
                    d0[0] = make_float4(hv.x, hv.x, hv.y, hv.y);
                    d0[1] = make_float4(hv.z, hv.z, hv.w, hv.w);
                }
            }
        }
    }

    // ================= conv tail =================
    if (tid < 32)
        poll_flag_sleep(&g_flags[(g * 32 + tid) * 32], base + Tn + 1);
    __syncthreads();

    float* scw  = sm_w;      // reuse
    float* sred = sm_r;
    for (int i = tid; i < Hn; i += NTHR) scw[i] = cw[i];
    const float cbv = cb[0];
    __syncthreads();

    const int cbl = tid & 15, hq = tid >> 4;     // 16 h-chunks of 32
    for (int j = 0; j < Tn / GC; ++j) {
        int t = c * (Tn / GC) + j;
        const float* hp2 = g_hist + ((size_t)(t + 1) * NG + g) * HB2 + cbl;
        float acc = 0.f;
        #pragma unroll 8
        for (int h = hq * 32; h < hq * 32 + 32; ++h)
            acc += __ldcg(hp2 + (size_t)h * BG) * scw[h];
        sred[tid] = acc;
        __syncthreads();
        if (tid < 16) {
            float s = cbv;
            #pragma unroll
            for (int q = 0; q < 16; ++q) s += sred[q * 16 + tid];
            out[(size_t)(g * 16 + tid) * Tn + t] = s;
        }
        __syncthreads();
    }
}

// ---------------------------------------------------------------------------
extern "C" void kernel_launch(void* const* d_in, const int* in_sizes, int n_in,
                              void* d_out, int out_size)
{
    const float* x    = (const float*)d_in[0];
    const float* W_ih = (const float*)d_in[1];
    const float* W_hh = (const float*)d_in[2];
    const float* b_ih = (const float*)d_in[3];
    const float* b_hh = (const float*)d_in[4];
    const float* cw   = (const float*)d_in[5];
    const float* cb   = (const float*)d_in[6];
    float* out = (float*)d_out;

    cudaFuncSetAttribute(lstm_fused_kernel,
                         cudaFuncAttributeMaxDynamicSharedMemorySize, SMEM_BYTES);
    lstm_fused_kernel<<<NCTA, NTHR, SMEM_BYTES>>>(x, W_ih, W_hh, b_ih, b_hh,
                                                  cw, cb, out);
}